// round 16
// baseline (speedup 1.0000x reference)
#include <cuda_runtime.h>
#include <cuda_fp16.h>
#include <cstdint>

// Problem sizes (fixed)
#define B_DIM 8192
#define F_DIM 1024
#define D_DIM 8192
#define C_DIM 512
#define K1    1024           // plain fp16 GEMM, no split (error budget verified R15)
#define NK1   (K1 / 64)      // 16 BK=64 steps for GEMM1
#define NK2   (D_DIM / 64)   // 128 BK=64 steps for IMMA

// Static device scratch (no allocation)
__device__ __half      g_Xh[(size_t)B_DIM * K1];        // 16 MB X fp16
__device__ __half      g_Wh[(size_t)F_DIM * D_DIM];     // 16 MB W fp16
__device__ signed char g_enc8[(size_t)B_DIM * D_DIM];   // 64 MB enc {0,1} bytes
__device__ signed char g_hv8[(size_t)C_DIM * D_DIM];    // 4 MB hv' {+1,-1}
__device__ int         g_rsh[C_DIM];                    // rowsum_h per class

__device__ __forceinline__ void cpa16(uint32_t dst, const void* src) {
    asm volatile("cp.async.cg.shared.global [%0], [%1], 16;"
                 :: "r"(dst), "l"(src) : "memory");
}
#define CP_COMMIT() asm volatile("cp.async.commit_group;" ::: "memory")
#define CP_WAIT1()  asm volatile("cp.async.wait_group 1;"  ::: "memory")

// GEMM1 smem stage (BK=64): A 128 x (64h + 8h pad) = 18432 B (144 B/row),
//                           B 64 x (128h + 8h pad) = 17408 B (272 B/row)
#define A_BYTES 18432
#define A_ROW_B 144
#define B_ROW_B 272
#define STAGE_BYTES 35840
#define SMEM_TOTAL (3 * STAGE_BYTES)       // 107520; x2 CTAs = 215 KB <= 228 KB/SM
// IMMA smem stage: A 128x(64+16pad) s8 = 10240 B, B same
#define A2_BYTES 10240
#define STAGE2_BYTES 20480
#define SMEM2_TOTAL (3 * STAGE2_BYTES)     // 61440

// ---------------------------------------------------------------------------
// Convert X[B,F] fp32 -> fp16 (plain round).
// ---------------------------------------------------------------------------
__global__ void convert_x_kernel(const float* __restrict__ X)
{
    int idx = blockIdx.x * blockDim.x + threadIdx.x;
    if (idx >= B_DIM * F_DIM / 4) return;
    float4 v = *reinterpret_cast<const float4*>(&X[(size_t)idx * 4]);
    unsigned short h0 = __half_as_ushort(__float2half_rn(v.x));
    unsigned short h1 = __half_as_ushort(__float2half_rn(v.y));
    unsigned short h2 = __half_as_ushort(__float2half_rn(v.z));
    unsigned short h3 = __half_as_ushort(__float2half_rn(v.w));
    uint2 hw = make_uint2((unsigned)h0 | ((unsigned)h1 << 16),
                          (unsigned)h2 | ((unsigned)h3 << 16));
    *reinterpret_cast<uint2*>(&g_Xh[(size_t)idx * 4]) = hw;
}

// ---------------------------------------------------------------------------
// Convert W[F,D] fp32 -> fp16 (plain round).
// ---------------------------------------------------------------------------
__global__ void convert_w_kernel(const float* __restrict__ W)
{
    int idx = blockIdx.x * blockDim.x + threadIdx.x;
    if (idx >= F_DIM * D_DIM / 4) return;
    float4 v = *reinterpret_cast<const float4*>(&W[(size_t)idx * 4]);
    unsigned short h0 = __half_as_ushort(__float2half_rn(v.x));
    unsigned short h1 = __half_as_ushort(__float2half_rn(v.y));
    unsigned short h2 = __half_as_ushort(__float2half_rn(v.z));
    unsigned short h3 = __half_as_ushort(__float2half_rn(v.w));
    uint2 hw = make_uint2((unsigned)h0 | ((unsigned)h1 << 16),
                          (unsigned)h2 | ((unsigned)h3 << 16));
    *reinterpret_cast<uint2*>(&g_Wh[(size_t)idx * 4]) = hw;
}

// ---------------------------------------------------------------------------
// Kernel 1: fp16 HMMA GEMM  Xh[B,K1] @ Wh[K1,D], fp32 accum, fused sign->s8.
// CTA 128x128, 256 threads (8 warps 2x4), warp 64x32, BK=64 (16 iters,
// half the barrier count of R15), 3-stage cp.async pipeline, 2 CTAs/SM.
// Same mma order as R15 -> bit-identical accumulation.
// ---------------------------------------------------------------------------
__global__ __launch_bounds__(256, 2)
void gemm_mma_binpack_kernel()
{
    extern __shared__ __align__(16) char smem[];

    const int tid  = threadIdx.x;
    const int wid  = tid >> 5;
    const int lane = tid & 31;
    const int bm = blockIdx.y * 128;
    const int bn = blockIdx.x * 128;

    const int wm = (wid >> 2) * 64;   // 0 or 64
    const int wn = (wid & 3) * 32;    // 0,32,64,96

    float acc[4][4][4];
#pragma unroll
    for (int i = 0; i < 4; i++)
#pragma unroll
        for (int j = 0; j < 4; j++)
#pragma unroll
            for (int r = 0; r < 4; r++) acc[i][j][r] = 0.0f;

    const int lg = lane >> 3;
    const int lr = lane & 7;

    uint32_t smem_u32_base;
    asm("{ .reg .u64 t; cvta.to.shared.u64 t, %1; cvt.u32.u64 %0, t; }"
        : "=r"(smem_u32_base) : "l"(smem));

    auto load_stage = [&](int kt, int buf) {
        const uint32_t ab = smem_u32_base + buf * STAGE_BYTES;
        const uint32_t bb = ab + A_BYTES;
        // A: 128 rows x 64 halfs = 1024 x 16B chunks, 4/thread
#pragma unroll
        for (int u = 0; u < 4; u++) {
            int idx = tid + u * 256;
            int row = idx >> 3;            // 0..127
            int ch  = idx & 7;             // 8 chunks of 16B per 128B row
            cpa16(ab + row * A_ROW_B + ch * 16,
                  &g_Xh[(size_t)(bm + row) * K1 + kt + ch * 8]);
        }
        // B: 64 krows x 128 halfs = 1024 x 16B chunks, 4/thread
#pragma unroll
        for (int u = 0; u < 4; u++) {
            int idx = tid + u * 256;
            int kr = idx >> 4;             // 0..63
            int ch = idx & 15;             // 16 chunks of 16B per 256B row
            cpa16(bb + kr * B_ROW_B + ch * 16,
                  &g_Wh[(size_t)(kt + kr) * D_DIM + bn + ch * 8]);
        }
    };

    load_stage(0, 0);  CP_COMMIT();
    load_stage(64, 1); CP_COMMIT();

    for (int it = 0; it < NK1; it++) {
        CP_WAIT1();
        __syncthreads();

        if (it + 2 < NK1) load_stage((it + 2) * 64, (it + 2) % 3);
        CP_COMMIT();

        const char* As = smem + (it % 3) * STAGE_BYTES;
        const char* Bs = As + A_BYTES;

#pragma unroll
        for (int kk = 0; kk < 64; kk += 16) {
            unsigned a[4][4];
#pragma unroll
            for (int i = 0; i < 4; i++) {
                int row = wm + i * 16 + lr + (lg & 1) * 8;
                int col = kk + (lg >> 1) * 8;
                unsigned addr = (unsigned)__cvta_generic_to_shared(
                    As + row * A_ROW_B + col * 2);
                asm volatile(
                    "ldmatrix.sync.aligned.m8n8.x4.shared.b16 {%0,%1,%2,%3}, [%4];"
                    : "=r"(a[i][0]), "=r"(a[i][1]), "=r"(a[i][2]), "=r"(a[i][3])
                    : "r"(addr));
            }
            unsigned bfr[4][2];
#pragma unroll
            for (int j = 0; j < 2; j++) {
                int krow = kk + lr + (lg & 1) * 8;
                int col  = wn + j * 16 + (lg >> 1) * 8;
                unsigned addr = (unsigned)__cvta_generic_to_shared(
                    Bs + krow * B_ROW_B + col * 2);
                unsigned r0, r1, r2, r3;
                asm volatile(
                    "ldmatrix.sync.aligned.m8n8.x4.trans.shared.b16 {%0,%1,%2,%3}, [%4];"
                    : "=r"(r0), "=r"(r1), "=r"(r2), "=r"(r3)
                    : "r"(addr));
                bfr[j * 2 + 0][0] = r0; bfr[j * 2 + 0][1] = r1;
                bfr[j * 2 + 1][0] = r2; bfr[j * 2 + 1][1] = r3;
            }
#pragma unroll
            for (int i = 0; i < 4; i++)
#pragma unroll
                for (int j = 0; j < 4; j++) {
                    asm volatile(
                        "mma.sync.aligned.m16n8k16.row.col.f32.f16.f16.f32 "
                        "{%0,%1,%2,%3}, {%4,%5,%6,%7}, {%8,%9}, {%0,%1,%2,%3};"
                        : "+f"(acc[i][j][0]), "+f"(acc[i][j][1]),
                          "+f"(acc[i][j][2]), "+f"(acc[i][j][3])
                        : "r"(a[i][0]), "r"(a[i][1]), "r"(a[i][2]), "r"(a[i][3]),
                          "r"(bfr[j][0]), "r"(bfr[j][1]));
                }
        }
        __syncthreads();
    }

    // --- epilogue: signs -> SB bytes (128x128, aliases stage buffers) ---
    unsigned char* SB = reinterpret_cast<unsigned char*>(smem);
    const int qr = lane >> 2;
    const int qc = (lane & 3) * 2;
#pragma unroll
    for (int i = 0; i < 4; i++)
#pragma unroll
        for (int j = 0; j < 4; j++) {
            int row0 = wm + i * 16 + qr;
            int col0 = wn + j * 8 + qc;
            SB[row0 * 128 + col0]           = (acc[i][j][0] >= 0.0f) ? 1 : 0;
            SB[row0 * 128 + col0 + 1]       = (acc[i][j][1] >= 0.0f) ? 1 : 0;
            SB[(row0 + 8) * 128 + col0]     = (acc[i][j][2] >= 0.0f) ? 1 : 0;
            SB[(row0 + 8) * 128 + col0 + 1] = (acc[i][j][3] >= 0.0f) ? 1 : 0;
        }
    __syncthreads();

    // vectorized copy SB -> g_enc8: 1024 x 16B chunks, 4 per thread
#pragma unroll
    for (int u = 0; u < 4; u++) {
        int idx = tid + u * 256;
        int row = idx >> 3;
        int ch  = idx & 7;
        uint4 v = *reinterpret_cast<const uint4*>(SB + row * 128 + ch * 16);
        *reinterpret_cast<uint4*>(
            &g_enc8[(size_t)(bm + row) * D_DIM + bn + ch * 16]) = v;
    }
}

// ---------------------------------------------------------------------------
// Kernel 2: classes_hv {0,1} floats -> hv' = 1-2h in s8, plus rowsum_h[c].
// ---------------------------------------------------------------------------
__global__ void convert_hv_kernel(const float* __restrict__ HV)
{
    __shared__ int red[256];
    const int c   = blockIdx.x;
    const int tid = threadIdx.x;
    int sum = 0;
#pragma unroll
    for (int it = 0; it < 8; it++) {
        int d = (it * 256 + tid) * 4;
        float4 f = *reinterpret_cast<const float4*>(&HV[(size_t)c * D_DIM + d]);
        int h0 = f.x > 0.5f, h1 = f.y > 0.5f, h2 = f.z > 0.5f, h3 = f.w > 0.5f;
        sum += h0 + h1 + h2 + h3;
        char4 v;
        v.x = (char)(1 - 2 * h0); v.y = (char)(1 - 2 * h1);
        v.z = (char)(1 - 2 * h2); v.w = (char)(1 - 2 * h3);
        *reinterpret_cast<char4*>(&g_hv8[(size_t)c * D_DIM + d]) = v;
    }
    red[tid] = sum;
    __syncthreads();
    for (int s = 128; s > 0; s >>= 1) {
        if (tid < s) red[tid] += red[tid + s];
        __syncthreads();
    }
    if (tid == 0) g_rsh[c] = red[0];
}

// ---------------------------------------------------------------------------
// Kernel 3: s8 IMMA GEMM  enc8[B,D] @ hv8[C,D]^T, + rowsum_h[c] -> float out.
// (unchanged — verified R11-R15; writes every output element)
// ---------------------------------------------------------------------------
__global__ __launch_bounds__(256, 2)
void imma_resp_kernel(float* __restrict__ OUT)
{
    extern __shared__ __align__(16) char smem[];

    const int tid  = threadIdx.x;
    const int wid  = tid >> 5;
    const int lane = tid & 31;
    const int bm = blockIdx.y * 128;
    const int bn = blockIdx.x * 128;

    const int wm = (wid >> 2) * 64;
    const int wn = (wid & 3) * 32;

    int acc[4][4][4];
#pragma unroll
    for (int i = 0; i < 4; i++)
#pragma unroll
        for (int j = 0; j < 4; j++)
#pragma unroll
            for (int r = 0; r < 4; r++) acc[i][j][r] = 0;

    const int lg = lane >> 3;
    const int lr = lane & 7;

    uint32_t smem_u32_base;
    asm("{ .reg .u64 t; cvta.to.shared.u64 t, %1; cvt.u32.u64 %0, t; }"
        : "=r"(smem_u32_base) : "l"(smem));

    auto load_stage = [&](int kt, int buf) {
        const uint32_t ab = smem_u32_base + buf * STAGE2_BYTES;
        const uint32_t bb = ab + A2_BYTES;
#pragma unroll
        for (int u = 0; u < 2; u++) {
            int idx = tid + u * 256;
            int row = idx >> 2;
            int ch  = idx & 3;
            cpa16(ab + row * 80 + ch * 16,
                  &g_enc8[(size_t)(bm + row) * D_DIM + kt + ch * 16]);
        }
#pragma unroll
        for (int u = 0; u < 2; u++) {
            int idx = tid + u * 256;
            int row = idx >> 2;
            int ch  = idx & 3;
            cpa16(bb + row * 80 + ch * 16,
                  &g_hv8[(size_t)(bn + row) * D_DIM + kt + ch * 16]);
        }
    };

    load_stage(0, 0);  CP_COMMIT();
    load_stage(64, 1); CP_COMMIT();

    for (int it = 0; it < NK2; it++) {
        CP_WAIT1();
        __syncthreads();

        if (it + 2 < NK2) load_stage((it + 2) * 64, (it + 2) % 3);
        CP_COMMIT();

        const char* As = smem + (it % 3) * STAGE2_BYTES;
        const char* Bs = As + A2_BYTES;

#pragma unroll
        for (int kkb = 0; kkb < 64; kkb += 32) {
            unsigned a[4][4];
#pragma unroll
            for (int i = 0; i < 4; i++) {
                int row = wm + i * 16 + lr + (lg & 1) * 8;
                int col = kkb + (lg >> 1) * 16;
                unsigned addr =
                    (unsigned)__cvta_generic_to_shared(As + row * 80 + col);
                asm volatile(
                    "ldmatrix.sync.aligned.m8n8.x4.shared.b16 {%0,%1,%2,%3}, [%4];"
                    : "=r"(a[i][0]), "=r"(a[i][1]), "=r"(a[i][2]), "=r"(a[i][3])
                    : "r"(addr));
            }
            unsigned bfr[4][2];
#pragma unroll
            for (int j = 0; j < 2; j++) {
                int row = wn + j * 16 + lr + (lg >> 1) * 8;
                int col = kkb + (lg & 1) * 16;
                unsigned addr =
                    (unsigned)__cvta_generic_to_shared(Bs + row * 80 + col);
                unsigned r0, r1, r2, r3;
                asm volatile(
                    "ldmatrix.sync.aligned.m8n8.x4.shared.b16 {%0,%1,%2,%3}, [%4];"
                    : "=r"(r0), "=r"(r1), "=r"(r2), "=r"(r3)
                    : "r"(addr));
                bfr[j * 2 + 0][0] = r0; bfr[j * 2 + 0][1] = r1;
                bfr[j * 2 + 1][0] = r2; bfr[j * 2 + 1][1] = r3;
            }
#pragma unroll
            for (int i = 0; i < 4; i++)
#pragma unroll
                for (int j = 0; j < 4; j++) {
                    asm volatile(
                        "mma.sync.aligned.m16n8k32.row.col.s32.s8.s8.s32 "
                        "{%0,%1,%2,%3}, {%4,%5,%6,%7}, {%8,%9}, {%0,%1,%2,%3};"
                        : "+r"(acc[i][j][0]), "+r"(acc[i][j][1]),
                          "+r"(acc[i][j][2]), "+r"(acc[i][j][3])
                        : "r"(a[i][0]), "r"(a[i][1]), "r"(a[i][2]), "r"(a[i][3]),
                          "r"(bfr[j][0]), "r"(bfr[j][1]));
                }
        }
        __syncthreads();
    }

    const int qr = lane >> 2;
    const int qc = (lane & 3) * 2;
#pragma unroll
    for (int i = 0; i < 4; i++)
#pragma unroll
        for (int j = 0; j < 4; j++) {
            int row0 = bm + wm + i * 16 + qr;
            int col0 = bn + wn + j * 8 + qc;
            int r0 = g_rsh[col0];
            int r1 = g_rsh[col0 + 1];
            OUT[(size_t)row0 * C_DIM + col0]           = (float)(acc[i][j][0] + r0);
            OUT[(size_t)row0 * C_DIM + col0 + 1]       = (float)(acc[i][j][1] + r1);
            OUT[(size_t)(row0 + 8) * C_DIM + col0]     = (float)(acc[i][j][2] + r0);
            OUT[(size_t)(row0 + 8) * C_DIM + col0 + 1] = (float)(acc[i][j][3] + r1);
        }
}

// ---------------------------------------------------------------------------
// Launch: convert X,W -> GEMM1(sign bytes) -> convert hv -> IMMA.
// (fill_out diagnostic dropped: IMMA writes every output element.)
// ---------------------------------------------------------------------------
extern "C" void kernel_launch(void* const* d_in, const int* in_sizes, int n_in,
                              void* d_out, int out_size)
{
    const float* x  = (const float*)d_in[0];   // [8192, 1024]
    const float* W  = (const float*)d_in[1];   // [1024, 8192]
    const float* hv = (const float*)d_in[2];   // [512, 8192]
    float* out = (float*)d_out;                // [8192, 512] float32

    cudaFuncSetAttribute(gemm_mma_binpack_kernel,
                         cudaFuncAttributeMaxDynamicSharedMemorySize, SMEM_TOTAL);
    cudaFuncSetAttribute(imma_resp_kernel,
                         cudaFuncAttributeMaxDynamicSharedMemorySize, SMEM2_TOTAL);

    convert_x_kernel<<<(B_DIM * F_DIM / 4 + 255) / 256, 256>>>(x);
    convert_w_kernel<<<(F_DIM * D_DIM / 4 + 255) / 256, 256>>>(W);

    dim3 g1(D_DIM / 128, B_DIM / 128);         // (64, 64)
    gemm_mma_binpack_kernel<<<g1, 256, SMEM_TOTAL>>>();

    convert_hv_kernel<<<C_DIM, 256>>>(hv);

    dim3 g3(C_DIM / 128, B_DIM / 128);         // (4, 64)
    imma_resp_kernel<<<g3, 256, SMEM2_TOTAL>>>(out);
}